// round 1
// baseline (speedup 1.0000x reference)
#include <cuda_runtime.h>
#include <cuda_bf16.h>
#include <math.h>

#define NE 8
#define NH 1024
#define NI 2816
#define TOPK 2
#define NT 2048
#define NP (NT * TOPK)   // 4096 token-expert pairs

#define BM 64
#define BN 64
#define BK 16

// Scratch (device globals — no allocation in kernel_launch)
__device__ int   g_perm[NP];
__device__ int   g_off[NE + 1];
__device__ float g_act[(size_t)NP * NI];   // silu(gate)*up, grouped-by-expert row order
__device__ float g_y[(size_t)NP * NH];     // weighted down-proj output, indexed by pair id

// ---------------------------------------------------------------------------
// Phase 1: routing — group pair ids by expert.
// Single block; counts + prefix + scatter. Row order within an expert is
// arbitrary but each row's VALUE is order-independent, and final combine is
// indexed by pair id, so the output is deterministic.
// ---------------------------------------------------------------------------
__global__ void route_kernel(const int* __restrict__ idx) {
    __shared__ int cnt[NE];
    __shared__ int cur[NE];
    int tid = threadIdx.x;
    if (tid < NE) cnt[tid] = 0;
    __syncthreads();
    for (int p = tid; p < NP; p += blockDim.x)
        atomicAdd(&cnt[idx[p]], 1);
    __syncthreads();
    if (tid == 0) {
        int s = 0;
        for (int e = 0; e < NE; e++) { g_off[e] = s; cur[e] = s; s += cnt[e]; }
        g_off[NE] = s;
    }
    __syncthreads();
    for (int p = tid; p < NP; p += blockDim.x) {
        int e = idx[p];
        int pos = atomicAdd(&cur[e], 1);
        g_perm[pos] = p;
    }
}

// ---------------------------------------------------------------------------
// Phase 2: gate+up GEMM with gathered A and fused SiLU*up epilogue.
//   act[r, i] = silu(x_r @ wg_e) * (x_r @ wu_e)      (r = grouped row)
// A: gathered rows of X [rows, H]; B: wg/wu [H, I] row-major.
// ---------------------------------------------------------------------------
__global__ __launch_bounds__(256) void gemm_gu_kernel(
    const float* __restrict__ X,
    const float* __restrict__ Wg,
    const float* __restrict__ Wu)
{
    int e    = blockIdx.z;
    int seg0 = g_off[e];
    int rows = g_off[e + 1] - seg0;
    int m0   = blockIdx.y * BM;
    if (m0 >= rows) return;
    int n0 = blockIdx.x * BN;

    const float* wg = Wg + (size_t)e * NH * NI;
    const float* wu = Wu + (size_t)e * NH * NI;

    __shared__ __align__(16) float As[BK][BM];
    __shared__ __align__(16) float Bg[BK][BN];
    __shared__ __align__(16) float Bu[BK][BN];

    int tid = threadIdx.x;
    int ty = tid >> 4, tx = tid & 15;           // 16x16 thread grid, 4x4 per thread
    int lm = tid >> 2, lk = (tid & 3) * 4;      // A-load: 4 threads per row
    int bk = tid >> 4, bn = (tid & 15) * 4;     // B-load: float4 per thread

    int token = -1;
    if (m0 + lm < rows) token = g_perm[seg0 + m0 + lm] / TOPK;
    const float* xrow = (token >= 0) ? (X + (size_t)token * NH) : X;

    float accg[4][4]; float accu[4][4];
    #pragma unroll
    for (int i = 0; i < 4; i++)
        #pragma unroll
        for (int j = 0; j < 4; j++) { accg[i][j] = 0.f; accu[i][j] = 0.f; }

    for (int k0 = 0; k0 < NH; k0 += BK) {
        float4 av = make_float4(0.f, 0.f, 0.f, 0.f);
        if (token >= 0) av = *(const float4*)(xrow + k0 + lk);
        As[lk + 0][lm] = av.x; As[lk + 1][lm] = av.y;
        As[lk + 2][lm] = av.z; As[lk + 3][lm] = av.w;
        *(float4*)&Bg[bk][bn] = *(const float4*)(wg + (size_t)(k0 + bk) * NI + n0 + bn);
        *(float4*)&Bu[bk][bn] = *(const float4*)(wu + (size_t)(k0 + bk) * NI + n0 + bn);
        __syncthreads();
        #pragma unroll
        for (int kk = 0; kk < BK; kk++) {
            float4 a4  = *(const float4*)&As[kk][ty * 4];
            float4 g4  = *(const float4*)&Bg[kk][tx * 4];
            float4 u4  = *(const float4*)&Bu[kk][tx * 4];
            float ar[4] = {a4.x, a4.y, a4.z, a4.w};
            float gr[4] = {g4.x, g4.y, g4.z, g4.w};
            float ur[4] = {u4.x, u4.y, u4.z, u4.w};
            #pragma unroll
            for (int i = 0; i < 4; i++)
                #pragma unroll
                for (int j = 0; j < 4; j++) {
                    accg[i][j] = fmaf(ar[i], gr[j], accg[i][j]);
                    accu[i][j] = fmaf(ar[i], ur[j], accu[i][j]);
                }
        }
        __syncthreads();
    }

    #pragma unroll
    for (int i = 0; i < 4; i++) {
        int r = m0 + ty * 4 + i;
        if (r >= rows) continue;
        size_t row = (size_t)(seg0 + r);
        #pragma unroll
        for (int j = 0; j < 4; j++) {
            float g = accg[i][j];
            float u = accu[i][j];
            float s = g / (1.f + expf(-g));   // silu
            g_act[row * NI + n0 + tx * 4 + j] = s * u;
        }
    }
}

// ---------------------------------------------------------------------------
// Phase 3: down GEMM.  y[pair, h] = w_pair * (act_row @ wd_e)
// A: act [rows, I] contiguous (grouped order); B: wd [I, H] row-major.
// Epilogue scatters by pair id with the routing weight applied — no atomics.
// ---------------------------------------------------------------------------
__global__ __launch_bounds__(256) void gemm_down_kernel(
    const float* __restrict__ Wd,
    const float* __restrict__ tkv)
{
    int e    = blockIdx.z;
    int seg0 = g_off[e];
    int rows = g_off[e + 1] - seg0;
    int m0   = blockIdx.y * BM;
    if (m0 >= rows) return;
    int n0 = blockIdx.x * BN;

    const float* wd = Wd + (size_t)e * NI * NH;

    __shared__ __align__(16) float As[BK][BM];
    __shared__ __align__(16) float Bs[BK][BN];

    int tid = threadIdx.x;
    int ty = tid >> 4, tx = tid & 15;
    int lm = tid >> 2, lk = (tid & 3) * 4;
    int bk = tid >> 4, bn = (tid & 15) * 4;

    bool mvalid = (m0 + lm < rows);
    const float* arow = g_act + (size_t)(seg0 + m0 + lm) * NI;

    float acc[4][4];
    #pragma unroll
    for (int i = 0; i < 4; i++)
        #pragma unroll
        for (int j = 0; j < 4; j++) acc[i][j] = 0.f;

    for (int k0 = 0; k0 < NI; k0 += BK) {
        float4 av = make_float4(0.f, 0.f, 0.f, 0.f);
        if (mvalid) av = *(const float4*)(arow + k0 + lk);
        As[lk + 0][lm] = av.x; As[lk + 1][lm] = av.y;
        As[lk + 2][lm] = av.z; As[lk + 3][lm] = av.w;
        *(float4*)&Bs[bk][bn] = *(const float4*)(wd + (size_t)(k0 + bk) * NH + n0 + bn);
        __syncthreads();
        #pragma unroll
        for (int kk = 0; kk < BK; kk++) {
            float4 a4 = *(const float4*)&As[kk][ty * 4];
            float4 b4 = *(const float4*)&Bs[kk][tx * 4];
            float ar[4] = {a4.x, a4.y, a4.z, a4.w};
            float br[4] = {b4.x, b4.y, b4.z, b4.w};
            #pragma unroll
            for (int i = 0; i < 4; i++)
                #pragma unroll
                for (int j = 0; j < 4; j++)
                    acc[i][j] = fmaf(ar[i], br[j], acc[i][j]);
        }
        __syncthreads();
    }

    #pragma unroll
    for (int i = 0; i < 4; i++) {
        int r = m0 + ty * 4 + i;
        if (r >= rows) continue;
        int pair = g_perm[seg0 + r];
        float w  = tkv[pair];
        #pragma unroll
        for (int j = 0; j < 4; j++)
            g_y[(size_t)pair * NH + n0 + tx * 4 + j] = w * acc[i][j];
    }
}

// ---------------------------------------------------------------------------
// Phase 4: combine — out[t] = y[2t] + y[2t+1]  (deterministic, no atomics)
// ---------------------------------------------------------------------------
__global__ void combine_kernel(float* __restrict__ out) {
    int i = blockIdx.x * blockDim.x + threadIdx.x;   // over T*H
    if (i >= NT * NH) return;
    int t = i / NH;
    int h = i - t * NH;
    size_t b0 = (size_t)(t * TOPK) * NH + h;
    out[i] = g_y[b0] + g_y[b0 + NH];
}

// ---------------------------------------------------------------------------
extern "C" void kernel_launch(void* const* d_in, const int* in_sizes, int n_in,
                              void* d_out, int out_size) {
    const float* X   = (const float*)d_in[0];   // [T, H]
    const int*   idx = (const int*)  d_in[1];   // [T, K]
    const float* tkv = (const float*)d_in[2];   // [T, K]
    const float* Wg  = (const float*)d_in[3];   // [E, H, I]
    const float* Wu  = (const float*)d_in[4];   // [E, H, I]
    const float* Wd  = (const float*)d_in[5];   // [E, I, H]
    float* out = (float*)d_out;                 // [T, H]

    route_kernel<<<1, 256>>>(idx);

    dim3 g2(NI / BN, (NP + BM - 1) / BM, NE);   // (44, 64, 8) — most row tiles exit early
    gemm_gu_kernel<<<g2, 256>>>(X, Wg, Wu);

    dim3 g3(NH / BN, (NP + BM - 1) / BM, NE);   // (16, 64, 8)
    gemm_down_kernel<<<g3, 256>>>(Wd, tkv);

    combine_kernel<<<(NT * NH + 255) / 256, 256>>>(out);
}

// round 16
// speedup vs baseline: 1.2706x; 1.2706x over previous
#include <cuda_runtime.h>
#include <cuda_bf16.h>
#include <cstdint>
#include <math.h>

#define NE 8
#define NH 1024
#define NI 2816
#define TOPK 2
#define NT 2048
#define NP (NT * TOPK)

#define BM 128
#define BN 64
#define BK 32
#define GU_FBUF (BM*BK + 2*BN*BK)   // 8192 floats per buffer
#define DN_FBUF (BM*BK + BN*BK)     // 6144 floats per buffer

// ---------------- scratch ----------------
__device__ int   g_perm[NP];
__device__ int   g_off[NE + 1];
__device__ float g_act[(size_t)NP * NI];
__device__ float g_y[(size_t)NP * NH];

// ---------------- helpers ----------------
__device__ __forceinline__ uint32_t smem_u32(const void* p) {
    uint32_t a;
    asm("{ .reg .u64 t; cvta.to.shared.u64 t, %1; cvt.u32.u64 %0, t; }" : "=r"(a) : "l"(p));
    return a;
}
__device__ __forceinline__ void cp16(uint32_t dst, const void* src, int sz) {
    asm volatile("cp.async.ca.shared.global [%0], [%1], 16, %2;"
                 :: "r"(dst), "l"(src), "r"(sz));
}
__device__ __forceinline__ void cp4(uint32_t dst, const void* src) {
    asm volatile("cp.async.ca.shared.global [%0], [%1], 4;" :: "r"(dst), "l"(src));
}
__device__ __forceinline__ void cp_commit() { asm volatile("cp.async.commit_group;"); }
template<int N> __device__ __forceinline__ void cp_wait() {
    asm volatile("cp.async.wait_group %0;" :: "n"(N));
}
// D += A(16x8,row) * B(8x8,col), tf32 in, f32 accumulate
__device__ __forceinline__ void mma_tf32(float* c, const uint32_t* a, const uint32_t* b) {
    asm volatile("mma.sync.aligned.m16n8k8.row.col.f32.tf32.tf32.f32 "
        "{%0,%1,%2,%3}, {%4,%5,%6,%7}, {%8,%9}, {%0,%1,%2,%3};"
        : "+f"(c[0]), "+f"(c[1]), "+f"(c[2]), "+f"(c[3])
        : "r"(a[0]), "r"(a[1]), "r"(a[2]), "r"(a[3]), "r"(b[0]), "r"(b[1]));
}
// 3xTF32 split: x_hi = tf32(x), x_lo = tf32(x - x_hi)
__device__ __forceinline__ uint32_t f2tf(float x) {
    uint32_t r;
    asm("cvt.rna.tf32.f32 %0, %1;" : "=r"(r) : "f"(x));
    return r;
}
__device__ __forceinline__ void tf_split(float x, uint32_t& hi, uint32_t& lo) {
    hi = f2tf(x);
    lo = f2tf(x - __uint_as_float(hi));
}

// ---------------- Phase 1: routing ----------------
__global__ void route_kernel(const int* __restrict__ idx) {
    __shared__ int cnt[NE];
    __shared__ int cur[NE];
    int tid = threadIdx.x;
    if (tid < NE) cnt[tid] = 0;
    __syncthreads();
    for (int p = tid; p < NP; p += blockDim.x) atomicAdd(&cnt[idx[p]], 1);
    __syncthreads();
    if (tid == 0) {
        int s = 0;
        for (int e = 0; e < NE; e++) { g_off[e] = s; cur[e] = s; s += cnt[e]; }
        g_off[NE] = s;
    }
    __syncthreads();
    for (int p = tid; p < NP; p += blockDim.x) {
        int e = idx[p];
        g_perm[atomicAdd(&cur[e], 1)] = p;
    }
}

// ---------------- GU copy/compute helpers ----------------
__device__ __forceinline__ void gu_copy(uint32_t smb, int bsel,
    const float* asrc, int asz, const uint32_t* adst,
    const float* wg, const float* wu, int n0, int k0, int bk, int bn)
{
    uint32_t bo = (uint32_t)bsel * (GU_FBUF * 4);
    #pragma unroll
    for (int i = 0; i < 4; i++)
        cp16(adst[i] + bo, asrc + k0 + i * 4, asz);
    #pragma unroll
    for (int r = 0; r < 4; r++) {
        int k = r * 8 + bk;
        #pragma unroll
        for (int nh = 0; nh < 2; nh++) {
            int n = nh * 32 + bn;
            uint32_t doff = (uint32_t)(n * BK + (k ^ ((n & 7) << 2))) * 4;
            cp4(smb + bo + (BM*BK)*4 + doff,            wg + (size_t)(k0 + k) * NI + n0 + n);
            cp4(smb + bo + (BM*BK + BN*BK)*4 + doff,    wu + (size_t)(k0 + k) * NI + n0 + n);
        }
    }
}

__device__ __forceinline__ void gu_compute(const float* sbuf, int wm, int wn, int g4, int t4,
    float cg[2][4][4], float cu[2][4][4])
{
    const float* As = sbuf;
    const float* Bg = sbuf + BM*BK;
    const float* Bu = sbuf + BM*BK + BN*BK;
    #pragma unroll
    for (int kt = 0; kt < 4; kt++) {
        int kA = kt * 8 + t4;
        uint32_t ah[2][4], al[2][4];
        #pragma unroll
        for (int mt = 0; mt < 2; mt++) {
            int m = wm + mt * 16 + g4;
            int sw = (m & 7) << 2;
            tf_split(As[m * BK + (kA ^ sw)],           ah[mt][0], al[mt][0]);
            tf_split(As[(m + 8) * BK + (kA ^ sw)],     ah[mt][1], al[mt][1]);
            tf_split(As[m * BK + ((kA + 4) ^ sw)],     ah[mt][2], al[mt][2]);
            tf_split(As[(m + 8) * BK + ((kA + 4) ^ sw)], ah[mt][3], al[mt][3]);
        }
        #pragma unroll
        for (int nt = 0; nt < 4; nt++) {
            int n = wn + nt * 8 + g4;
            int sw = (n & 7) << 2;
            uint32_t bh[2], bl[2];
            // gate B
            tf_split(Bg[n * BK + (kA ^ sw)],       bh[0], bl[0]);
            tf_split(Bg[n * BK + ((kA + 4) ^ sw)], bh[1], bl[1]);
            mma_tf32(cg[0][nt], ah[0], bh);
            mma_tf32(cg[0][nt], al[0], bh);
            mma_tf32(cg[0][nt], ah[0], bl);
            mma_tf32(cg[1][nt], ah[1], bh);
            mma_tf32(cg[1][nt], al[1], bh);
            mma_tf32(cg[1][nt], ah[1], bl);
            // up B
            tf_split(Bu[n * BK + (kA ^ sw)],       bh[0], bl[0]);
            tf_split(Bu[n * BK + ((kA + 4) ^ sw)], bh[1], bl[1]);
            mma_tf32(cu[0][nt], ah[0], bh);
            mma_tf32(cu[0][nt], al[0], bh);
            mma_tf32(cu[0][nt], ah[0], bl);
            mma_tf32(cu[1][nt], ah[1], bh);
            mma_tf32(cu[1][nt], al[1], bh);
            mma_tf32(cu[1][nt], ah[1], bl);
        }
    }
}

// ---------------- Phase 2: GU GEMM (3xTF32 mma.sync) ----------------
__global__ __launch_bounds__(256, 2) void gemm_gu(
    const float* __restrict__ X,
    const float* __restrict__ Wg,
    const float* __restrict__ Wu)
{
    extern __shared__ float sm[];
    int e    = blockIdx.z;
    int seg0 = g_off[e];
    int rows = g_off[e + 1] - seg0;
    int m0   = blockIdx.y * BM;
    if (m0 >= rows) return;
    int n0 = blockIdx.x * BN;

    const float* wg = Wg + (size_t)e * NH * NI;
    const float* wu = Wu + (size_t)e * NH * NI;

    int tid = threadIdx.x, lane = tid & 31, w = tid >> 5;
    int wm = (w & 3) * 32, wn = (w >> 2) * 32;
    int g4 = lane >> 2, t4 = lane & 3;
    uint32_t smb = smem_u32(sm);

    // A copy: each thread owns one row (tid>>1) and 16 consecutive k
    int arow = tid >> 1;
    int aks  = (tid & 1) * 16;
    int asz  = (m0 + arow < rows) ? 16 : 0;
    const float* asrc = X;
    if (asz) asrc = X + (size_t)(g_perm[seg0 + m0 + arow] >> 1) * NH + aks;
    uint32_t adst[4];
    #pragma unroll
    for (int i = 0; i < 4; i++) {
        int k = aks + i * 4;
        adst[i] = smb + (uint32_t)(arow * BK + (k ^ ((arow & 7) << 2))) * 4;
    }
    int bk = tid >> 5, bn = tid & 31;

    float cg[2][4][4], cu[2][4][4];
    #pragma unroll
    for (int a = 0; a < 2; a++)
        #pragma unroll
        for (int b = 0; b < 4; b++)
            #pragma unroll
            for (int q = 0; q < 4; q++) { cg[a][b][q] = 0.f; cu[a][b][q] = 0.f; }

    const int nch = NH / BK;   // 32
    gu_copy(smb, 0, asrc, asz, adst, wg, wu, n0, 0, bk, bn);
    cp_commit();

    for (int c = 0; c < nch; c++) {
        if (c + 1 < nch) {
            gu_copy(smb, (c + 1) & 1, asrc, asz, adst, wg, wu, n0, (c + 1) * BK, bk, bn);
            cp_commit();
            cp_wait<1>();
        } else {
            cp_wait<0>();
        }
        __syncthreads();
        gu_compute(sm + (c & 1) * GU_FBUF, wm, wn, g4, t4, cg, cu);
        __syncthreads();
    }

    // epilogue: silu(g)*u -> g_act (float2 stores)
    #pragma unroll
    for (int mt = 0; mt < 2; mt++)
        #pragma unroll
        for (int h = 0; h < 2; h++) {
            int mloc = m0 + wm + mt * 16 + g4 + h * 8;
            if (mloc < rows) {
                float* dst = g_act + (size_t)(seg0 + mloc) * NI + n0 + wn;
                #pragma unroll
                for (int nt = 0; nt < 4; nt++) {
                    float g0 = cg[mt][nt][h * 2], g1 = cg[mt][nt][h * 2 + 1];
                    float u0 = cu[mt][nt][h * 2], u1 = cu[mt][nt][h * 2 + 1];
                    float2 o;
                    o.x = g0 / (1.f + __expf(-g0)) * u0;
                    o.y = g1 / (1.f + __expf(-g1)) * u1;
                    *(float2*)(dst + nt * 8 + t4 * 2) = o;
                }
            }
        }
}

// ---------------- Down copy/compute helpers ----------------
__device__ __forceinline__ void dn_copy(uint32_t smb, int bsel,
    const float* asrc, int asz, const uint32_t* adst,
    const float* wd, int n0, int k0, int bk, int bn)
{
    uint32_t bo = (uint32_t)bsel * (DN_FBUF * 4);
    #pragma unroll
    for (int i = 0; i < 4; i++)
        cp16(adst[i] + bo, asrc + k0 + i * 4, asz);
    #pragma unroll
    for (int r = 0; r < 4; r++) {
        int k = r * 8 + bk;
        #pragma unroll
        for (int nh = 0; nh < 2; nh++) {
            int n = nh * 32 + bn;
            uint32_t doff = (uint32_t)(n * BK + (k ^ ((n & 7) << 2))) * 4;
            cp4(smb + bo + (BM*BK)*4 + doff, wd + (size_t)(k0 + k) * NH + n0 + n);
        }
    }
}

__device__ __forceinline__ void dn_compute(const float* sbuf, int wm, int wn, int g4, int t4,
    float cd[2][4][4])
{
    const float* As = sbuf;
    const float* Bs = sbuf + BM*BK;
    #pragma unroll
    for (int kt = 0; kt < 4; kt++) {
        int kA = kt * 8 + t4;
        uint32_t ah[2][4], al[2][4];
        #pragma unroll
        for (int mt = 0; mt < 2; mt++) {
            int m = wm + mt * 16 + g4;
            int sw = (m & 7) << 2;
            tf_split(As[m * BK + (kA ^ sw)],             ah[mt][0], al[mt][0]);
            tf_split(As[(m + 8) * BK + (kA ^ sw)],       ah[mt][1], al[mt][1]);
            tf_split(As[m * BK + ((kA + 4) ^ sw)],       ah[mt][2], al[mt][2]);
            tf_split(As[(m + 8) * BK + ((kA + 4) ^ sw)], ah[mt][3], al[mt][3]);
        }
        #pragma unroll
        for (int nt = 0; nt < 4; nt++) {
            int n = wn + nt * 8 + g4;
            int sw = (n & 7) << 2;
            uint32_t bh[2], bl[2];
            tf_split(Bs[n * BK + (kA ^ sw)],       bh[0], bl[0]);
            tf_split(Bs[n * BK + ((kA + 4) ^ sw)], bh[1], bl[1]);
            mma_tf32(cd[0][nt], ah[0], bh);
            mma_tf32(cd[0][nt], al[0], bh);
            mma_tf32(cd[0][nt], ah[0], bl);
            mma_tf32(cd[1][nt], ah[1], bh);
            mma_tf32(cd[1][nt], al[1], bh);
            mma_tf32(cd[1][nt], ah[1], bl);
        }
    }
}

// ---------------- Phase 3: down GEMM (3xTF32 mma.sync) ----------------
__global__ __launch_bounds__(256, 2) void gemm_down(
    const float* __restrict__ Wd,
    const float* __restrict__ tkv)
{
    extern __shared__ float sm[];
    int e    = blockIdx.z;
    int seg0 = g_off[e];
    int rows = g_off[e + 1] - seg0;
    int m0   = blockIdx.y * BM;
    if (m0 >= rows) return;
    int n0 = blockIdx.x * BN;

    const float* wd = Wd + (size_t)e * NI * NH;

    int tid = threadIdx.x, lane = tid & 31, w = tid >> 5;
    int wm = (w & 3) * 32, wn = (w >> 2) * 32;
    int g4 = lane >> 2, t4 = lane & 3;
    uint32_t smb = smem_u32(sm);

    int arow = tid >> 1;
    int aks  = (tid & 1) * 16;
    int asz  = (m0 + arow < rows) ? 16 : 0;
    const float* asrc = g_act;
    if (asz) asrc = g_act + (size_t)(seg0 + m0 + arow) * NI + aks;
    uint32_t adst[4];
    #pragma unroll
    for (int i = 0; i < 4; i++) {
        int k = aks + i * 4;
        adst[i] = smb + (uint32_t)(arow * BK + (k ^ ((arow & 7) << 2))) * 4;
    }
    int bk = tid >> 5, bn = tid & 31;

    float cd[2][4][4];
    #pragma unroll
    for (int a = 0; a < 2; a++)
        #pragma unroll
        for (int b = 0; b < 4; b++)
            #pragma unroll
            for (int q = 0; q < 4; q++) cd[a][b][q] = 0.f;

    const int nch = NI / BK;   // 88
    dn_copy(smb, 0, asrc, asz, adst, wd, n0, 0, bk, bn);
    cp_commit();

    for (int c = 0; c < nch; c++) {
        if (c + 1 < nch) {
            dn_copy(smb, (c + 1) & 1, asrc, asz, adst, wd, n0, (c + 1) * BK, bk, bn);
            cp_commit();
            cp_wait<1>();
        } else {
            cp_wait<0>();
        }
        __syncthreads();
        dn_compute(sm + (c & 1) * DN_FBUF, wm, wn, g4, t4, cd);
        __syncthreads();
    }

    // epilogue: apply routing weight, scatter by pair id (deterministic)
    #pragma unroll
    for (int mt = 0; mt < 2; mt++)
        #pragma unroll
        for (int h = 0; h < 2; h++) {
            int mloc = m0 + wm + mt * 16 + g4 + h * 8;
            if (mloc < rows) {
                int pair = g_perm[seg0 + mloc];
                float wt = tkv[pair];
                float* dst = g_y + (size_t)pair * NH + n0 + wn;
                #pragma unroll
                for (int nt = 0; nt < 4; nt++) {
                    float2 o;
                    o.x = wt * cd[mt][nt][h * 2];
                    o.y = wt * cd[mt][nt][h * 2 + 1];
                    *(float2*)(dst + nt * 8 + t4 * 2) = o;
                }
            }
        }
}

// ---------------- Phase 4: combine ----------------
__global__ void combine_kernel(float* __restrict__ out) {
    int i = blockIdx.x * blockDim.x + threadIdx.x;
    if (i >= NT * NH) return;
    int t = i / NH;
    int h = i - t * NH;
    size_t b0 = (size_t)(t * TOPK) * NH + h;
    out[i] = g_y[b0] + g_y[b0 + NH];
}

// ---------------- launch ----------------
extern "C" void kernel_launch(void* const* d_in, const int* in_sizes, int n_in,
                              void* d_out, int out_size) {
    const float* X   = (const float*)d_in[0];
    const int*   idx = (const int*)  d_in[1];
    const float* tkv = (const float*)d_in[2];
    const float* Wg  = (const float*)d_in[3];
    const float* Wu  = (const float*)d_in[4];
    const float* Wd  = (const float*)d_in[5];
    float* out = (float*)d_out;

    cudaFuncSetAttribute(gemm_gu,   cudaFuncAttributeMaxDynamicSharedMemorySize, 2 * GU_FBUF * 4);
    cudaFuncSetAttribute(gemm_down, cudaFuncAttributeMaxDynamicSharedMemorySize, 2 * DN_FBUF * 4);

    route_kernel<<<1, 256>>>(idx);

    dim3 ggu(NI / BN, NP / BM, NE);   // (44, 32, 8); most M-tiles exit early
    gemm_gu<<<ggu, 256, 2 * GU_FBUF * 4>>>(X, Wg, Wu);

    dim3 gdn(NH / BN, NP / BM, NE);   // (16, 32, 8)
    gemm_down<<<gdn, 256, 2 * DN_FBUF * 4>>>(Wd, tkv);

    combine_kernel<<<(NT * NH + 255) / 256, 256>>>(out);
}